// round 3
// baseline (speedup 1.0000x reference)
#include <cuda_runtime.h>

#define NN     65536
#define VOCAB  1000
#define DIM    256
#define DIM3   768
#define MAXLV  192
#define TB     16

// ---------------- scratch (static device allocations only) ----------------
static __device__ float g_hsum [2 * NN * DIM];   // child h sums   (134 MB)
static __device__ float g_fcsum[2 * NN * DIM];   // child f*c sums (134 MB)
static __device__ float g_embp_iou[VOCAB * DIM3]; // emb@Wioux + bioux + biouh
static __device__ float g_embp_fx [VOCAB * DIM];  // emb@Wfx   + bfx   + bfh
static __device__ int   g_sched[2 * NN];
static __device__ int   g_par  [2 * NN];
static __device__ int   g_tok  [2 * NN];
static __device__ int   g_depth[2 * NN];
static __device__ int   g_cnt  [2 * MAXLV];
static __device__ int   g_cur  [2 * MAXLV];
static __device__ int   g_start[2 * MAXLV];
static __device__ int   g_lo[MAXLV];
static __device__ int   g_hi[MAXLV];
static __device__ float g_croot[2 * DIM];
static __device__ unsigned g_barcnt;   // zero-init, self-resetting
static __device__ unsigned g_bargen;   // monotone generation counter

__device__ __forceinline__ float sigm(float x) { return 1.0f / (1.0f + expf(-x)); }

// ---------------- phase 0: embedding projections (VOCAB only!) ----------------
__global__ void k_embproj(const float* __restrict__ emb,
                          const float* __restrict__ Wioux, const float* __restrict__ bioux,
                          const float* __restrict__ biouh,
                          const float* __restrict__ Wfx,   const float* __restrict__ bfx,
                          const float* __restrict__ bfh) {
  __shared__ float x[DIM];
  const int v = blockIdx.x, t = threadIdx.x;
  x[t] = emb[v * DIM + t];
  __syncthreads();
  float a0 = bioux[t]         + biouh[t];
  float a1 = bioux[DIM + t]   + biouh[DIM + t];
  float a2 = bioux[2*DIM + t] + biouh[2*DIM + t];
  float af = bfx[t] + bfh[t];
  #pragma unroll 4
  for (int k = 0; k < DIM; ++k) {
    const float xv = x[k];
    a0 = fmaf(xv, Wioux[k*DIM3 + t],          a0);
    a1 = fmaf(xv, Wioux[k*DIM3 + DIM + t],    a1);
    a2 = fmaf(xv, Wioux[k*DIM3 + 2*DIM + t],  a2);
    af = fmaf(xv, Wfx  [k*DIM  + t],          af);
  }
  g_embp_iou[v*DIM3 + t]          = a0;
  g_embp_iou[v*DIM3 + DIM + t]    = a1;
  g_embp_iou[v*DIM3 + 2*DIM + t]  = a2;
  g_embp_fx [v*DIM + t]           = af;
}

// ---------------- phase 1: node depths + per-(tree,level) histogram ----------------
__global__ void k_depth(const int* __restrict__ lpar, const int* __restrict__ rpar,
                        const int* __restrict__ ltok, const int* __restrict__ rtok) {
  const int g = blockIdx.x * blockDim.x + threadIdx.x;
  if (g >= 2 * NN) return;
  const int tree = g >> 16, node = g & (NN - 1);
  const int* par = tree ? rpar : lpar;
  const int* tok = tree ? rtok : ltok;
  int d = 0, i = node;
  while (i != 0) { i = par[i]; ++d; }   // parent[i] < i guarantees termination
  if (d > MAXLV - 1) d = MAXLV - 1;
  g_depth[g] = d;
  atomicAdd(&g_cnt[tree * MAXLV + d], 1);
  g_par[g] = (tree << 16) | par[node];
  g_tok[g] = tok[node];
}

// ---------------- phase 2: level offsets (descending depth layout) ----------------
__global__ void k_scan() {
  if (threadIdx.x == 0 && blockIdx.x == 0) {
    int off = 0;
    for (int L = MAXLV - 1; L >= 0; --L) {
      g_lo[L] = off;
      g_start[0 * MAXLV + L] = off; off += g_cnt[0 * MAXLV + L];
      g_start[1 * MAXLV + L] = off; off += g_cnt[1 * MAXLV + L];
      g_hi[L] = off;
    }
  }
}

// ---------------- phase 3: bucket nodes by level ----------------
__global__ void k_scatter() {
  const int g = blockIdx.x * blockDim.x + threadIdx.x;
  if (g >= 2 * NN) return;
  const int tree = g >> 16;
  const int d = g_depth[g];
  const int pos = g_start[tree * MAXLV + d] + atomicAdd(&g_cur[tree * MAXLV + d], 1);
  g_sched[pos] = g;
}

// ---------------- software grid barrier (all blocks resident by construction) ----------------
__device__ __forceinline__ void gbar() {
  __threadfence();
  __syncthreads();
  if (threadIdx.x == 0) {
    volatile unsigned* vg = &g_bargen;
    const unsigned my = *vg;
    const unsigned tkt = atomicAdd(&g_barcnt, 1u);
    if (tkt == gridDim.x - 1) {
      g_barcnt = 0;
      __threadfence();
      atomicAdd(&g_bargen, 1u);
    } else {
      while (*vg == my) { __nanosleep(64); }
    }
    __threadfence();
  }
  __syncthreads();
}

// ---------------- phase 4: persistent wavefront TreeLSTM ----------------
__global__ void __launch_bounds__(256, 2) k_levels(const float* __restrict__ Wiouh,
                                                   const float* __restrict__ Wfh) {
  __shared__ __align__(16) float hsh[TB][DIM];
  __shared__ int snode[TB], spar[TB], stok[TB], sptok[TB];
  const int t = threadIdx.x;

  for (int L = MAXLV - 1; L >= 0; --L) {
    const int lo = g_lo[L], hi = g_hi[L];
    const int cnt = hi - lo;
    if (cnt == 0) continue;                 // identical on all blocks: no barrier needed
    const int nch = (cnt + TB - 1) / TB;

    for (int ch = blockIdx.x; ch < nch; ch += gridDim.x) {
      const int base = lo + ch * TB;
      const int nb = min(TB, hi - base);
      __syncthreads();                      // previous chunk fully done with shared

      if (t < TB) {
        const int gg = (t < nb) ? g_sched[base + t] : -1;
        snode[t] = gg;
        if (gg >= 0) {
          const int pg = g_par[gg];
          spar[t]  = pg;
          stok[t]  = g_tok[gg];
          sptok[t] = g_tok[pg];
        }
      }
      __syncthreads();

      // load child-sum h vectors (L2-coherent loads: other SMs wrote via atomics)
      #pragma unroll
      for (int b = 0; b < TB; ++b) {
        const int gg = snode[b];
        hsh[b][t] = (gg >= 0) ? __ldcg(&g_hsum[gg * DIM + t]) : 0.0f;
      }

      // init iou accumulators from embedding projection gather (biases folded)
      float a0[TB], a1[TB], a2[TB];
      #pragma unroll
      for (int b = 0; b < TB; ++b) {
        const int gg = snode[b];
        if (gg >= 0) {
          const int tv = stok[b] * DIM3;
          a0[b] = g_embp_iou[tv + t];
          a1[b] = g_embp_iou[tv + DIM + t];
          a2[b] = g_embp_iou[tv + 2*DIM + t];
        } else { a0[b] = a1[b] = a2[b] = 0.0f; }
      }
      __syncthreads();

      // matvec 1: iou += h_sum @ Wiouh   (thread t owns outputs t, 256+t, 512+t)
      #pragma unroll 2
      for (int k4 = 0; k4 < DIM / 4; ++k4) {
        float w0[4], w1[4], w2[4];
        #pragma unroll
        for (int kk = 0; kk < 4; ++kk) {
          const float* wr = Wiouh + (k4*4 + kk) * DIM3 + t;
          w0[kk] = wr[0]; w1[kk] = wr[DIM]; w2[kk] = wr[2*DIM];
        }
        #pragma unroll
        for (int b = 0; b < TB; ++b) {
          const float4 hb = reinterpret_cast<const float4*>(hsh[b])[k4];
          a0[b] = fmaf(hb.x, w0[0], a0[b]); a0[b] = fmaf(hb.y, w0[1], a0[b]);
          a0[b] = fmaf(hb.z, w0[2], a0[b]); a0[b] = fmaf(hb.w, w0[3], a0[b]);
          a1[b] = fmaf(hb.x, w1[0], a1[b]); a1[b] = fmaf(hb.y, w1[1], a1[b]);
          a1[b] = fmaf(hb.z, w1[2], a1[b]); a1[b] = fmaf(hb.w, w1[3], a1[b]);
          a2[b] = fmaf(hb.x, w2[0], a2[b]); a2[b] = fmaf(hb.y, w2[1], a2[b]);
          a2[b] = fmaf(hb.z, w2[2], a2[b]); a2[b] = fmaf(hb.w, w2[3], a2[b]);
        }
      }

      // gates
      float cc[TB], hh[TB];
      #pragma unroll
      for (int b = 0; b < TB; ++b) {
        const int gg = snode[b];
        if (gg >= 0) {
          const float fcs = __ldcg(&g_fcsum[gg * DIM + t]);
          const float c = sigm(a0[b]) * tanhf(a2[b]) + fcs;
          const float h = sigm(a1[b]) * tanhf(c);
          cc[b] = c; hh[b] = h;
        } else { cc[b] = 0.0f; hh[b] = 0.0f; }
      }
      __syncthreads();                      // everyone done reading hsh (matvec1)
      #pragma unroll
      for (int b = 0; b < TB; ++b) hsh[b][t] = hh[b];
      __syncthreads();

      // matvec 2: fpre = h @ Wfh + (bfh + bfx + emb_p@Wfx) [folded in g_embp_fx]
      float f[TB];
      #pragma unroll
      for (int b = 0; b < TB; ++b)
        f[b] = (snode[b] >= 0) ? g_embp_fx[sptok[b] * DIM + t] : 0.0f;

      #pragma unroll 2
      for (int k4 = 0; k4 < DIM / 4; ++k4) {
        float w[4];
        #pragma unroll
        for (int kk = 0; kk < 4; ++kk) w[kk] = Wfh[(k4*4 + kk) * DIM + t];
        #pragma unroll
        for (int b = 0; b < TB; ++b) {
          const float4 hb = reinterpret_cast<const float4*>(hsh[b])[k4];
          f[b] = fmaf(hb.x, w[0], f[b]); f[b] = fmaf(hb.y, w[1], f[b]);
          f[b] = fmaf(hb.z, w[2], f[b]); f[b] = fmaf(hb.w, w[3], f[b]);
        }
      }

      // accumulate into parents (siblings may collide at same level -> atomics)
      #pragma unroll
      for (int b = 0; b < TB; ++b) {
        const int gg = snode[b];
        if (gg < 0) continue;
        if ((gg & (NN - 1)) == 0) {
          g_croot[(gg >> 16) * DIM + t] = cc[b];        // tree root: record c
        } else {
          const float ff = sigm(f[b]);
          atomicAdd(&g_hsum [spar[b] * DIM + t], hh[b]);
          atomicAdd(&g_fcsum[spar[b] * DIM + t], ff * cc[b]);
        }
      }
    }
    gbar();   // level complete on the whole grid
  }
}

// ---------------- phase 5: similarity head ----------------
__global__ void k_head(const float* __restrict__ Wh, const float* __restrict__ bh,
                       const float* __restrict__ Wp, const float* __restrict__ bp,
                       float* __restrict__ out) {
  __shared__ float vec[2 * DIM];
  __shared__ float s0[DIM], s1[DIM];
  const int t = threadIdx.x;
  const float cl = g_croot[t], cr = g_croot[DIM + t];
  vec[t] = cl * cr;
  vec[DIM + t] = fabsf(cl - cr);
  __syncthreads();
  float acc = bh[t];
  #pragma unroll 4
  for (int k = 0; k < 2 * DIM; ++k) acc = fmaf(vec[k], Wh[k * DIM + t], acc);
  const float hid = sigm(acc);
  s0[t] = hid * Wp[t * 2 + 0];
  s1[t] = hid * Wp[t * 2 + 1];
  __syncthreads();
  for (int s = DIM / 2; s > 0; s >>= 1) {
    if (t < s) { s0[t] += s0[t + s]; s1[t] += s1[t + s]; }
    __syncthreads();
  }
  if (t == 0) {
    const float l0 = s0[0] + bp[0], l1 = s1[0] + bp[1];
    const float m = fmaxf(l0, l1);
    const float e0 = expf(l0 - m), e1 = expf(l1 - m);
    const float inv = 1.0f / (e0 + e1);
    out[0] = e0 * inv;
    out[1] = e1 * inv;
  }
}

// ---------------- launcher (graph-capturable: launches + async memsets only) ----------------
extern "C" void kernel_launch(void* const* d_in, const int* in_sizes, int n_in,
                              void* d_out, int out_size) {
  (void)in_sizes; (void)n_in;
  const int*   l_tok = (const int*)  d_in[0];
  const int*   l_par = (const int*)  d_in[1];
  const int*   r_tok = (const int*)  d_in[2];
  const int*   r_par = (const int*)  d_in[3];
  const float* emb   = (const float*)d_in[4];
  const float* Wioux = (const float*)d_in[5];
  const float* bioux = (const float*)d_in[6];
  const float* Wiouh = (const float*)d_in[7];
  const float* biouh = (const float*)d_in[8];
  const float* Wfx   = (const float*)d_in[9];
  const float* bfx   = (const float*)d_in[10];
  const float* Wfh   = (const float*)d_in[11];
  const float* bfh   = (const float*)d_in[12];
  const float* Wh    = (const float*)d_in[13];
  const float* bh    = (const float*)d_in[14];
  const float* Wp    = (const float*)d_in[15];
  const float* bp    = (const float*)d_in[16];
  float* out = (float*)d_out;
  (void)out_size;

  void *p_hs, *p_fc, *p_cnt, *p_cur;
  cudaGetSymbolAddress(&p_hs,  g_hsum);
  cudaGetSymbolAddress(&p_fc,  g_fcsum);
  cudaGetSymbolAddress(&p_cnt, g_cnt);
  cudaGetSymbolAddress(&p_cur, g_cur);
  cudaMemsetAsync(p_hs,  0, sizeof(float) * 2ull * NN * DIM);
  cudaMemsetAsync(p_fc,  0, sizeof(float) * 2ull * NN * DIM);
  cudaMemsetAsync(p_cnt, 0, sizeof(int) * 2 * MAXLV);
  cudaMemsetAsync(p_cur, 0, sizeof(int) * 2 * MAXLV);

  k_embproj<<<VOCAB, DIM>>>(emb, Wioux, bioux, biouh, Wfx, bfx, bfh);
  k_depth<<<(2 * NN + 255) / 256, 256>>>(l_par, r_par, l_tok, r_tok);
  k_scan<<<1, 32>>>();
  k_scatter<<<(2 * NN + 255) / 256, 256>>>();

  int dev = 0;
  cudaGetDevice(&dev);
  int sms = 148;
  cudaDeviceGetAttribute(&sms, cudaDevAttrMultiProcessorCount, dev);
  k_levels<<<sms * 2, 256>>>(Wiouh, Wfh);   // __launch_bounds__(256,2) guarantees residency

  k_head<<<1, DIM>>>(Wh, bh, Wp, bp, out);
}

// round 6
// speedup vs baseline: 1.1160x; 1.1160x over previous
#include <cuda_runtime.h>

#define NN     65536
#define VOCAB  1000
#define DIM    256
#define DIM3   768
#define MAXLV  192
#define TB     16
#define PAD    20

// ---------------- scratch (static device allocations only) ----------------
static __device__ float g_hsum [2 * NN * DIM];    // child h sums   (134 MB)
static __device__ float g_fcsum[2 * NN * DIM];    // child f*c sums (134 MB)
static __device__ float g_embp_iou[VOCAB * DIM3]; // emb@Wioux + bioux + biouh
static __device__ float g_embp_fx [VOCAB * DIM];  // emb@Wfx   + bfx   + bfh
static __device__ float g_leaf_c  [VOCAB * DIM];  // leaf cell state per token
static __device__ float g_leaf_h  [VOCAB * DIM];  // leaf hidden per token
static __device__ float g_fpreL   [VOCAB * DIM];  // leaf_h @ Wfh per token
static __device__ int   g_sched[2 * NN];
static __device__ int   g_par  [2 * NN];
static __device__ int   g_tok  [2 * NN];
static __device__ int   g_depth[2 * NN];
static __device__ int   g_childcnt[2 * NN];
static __device__ int   g_cnt  [2 * MAXLV];
static __device__ int   g_cur  [2 * MAXLV];
static __device__ int   g_start[2 * MAXLV];
static __device__ int   g_lo[MAXLV];
static __device__ int   g_hi[MAXLV];
static __device__ float g_croot[2 * DIM];
static __device__ unsigned g_barcnt;   // zero-init, self-resetting
static __device__ unsigned g_bargen;   // monotone generation counter

__device__ __forceinline__ float sigm(float x) { return 1.0f / (1.0f + expf(-x)); }

// ---- f32x2 helpers (sm_100+; ptxas never auto-fuses FFMA2 from C++) ----
__device__ __forceinline__ unsigned long long pack2(float lo, float hi) {
  unsigned long long r;
  asm("mov.b64 %0, {%1, %2};" : "=l"(r) : "f"(lo), "f"(hi));
  return r;
}
__device__ __forceinline__ void unpack2(unsigned long long v, float& lo, float& hi) {
  asm("mov.b64 {%0, %1}, %2;" : "=f"(lo), "=f"(hi) : "l"(v));
}
#define FMA2(d, h, w) asm("fma.rn.f32x2 %0, %1, %2, %0;" : "+l"(d) : "l"(h), "l"(w))

// ---------------- phase 0: per-vocab projections + leaf tables ----------------
// 4 tokens per block: weight traffic /4. Also computes leaf c/h and fpreL = h@Wfh.
__global__ void k_embproj(const float* __restrict__ emb,
                          const float* __restrict__ Wioux, const float* __restrict__ bioux,
                          const float* __restrict__ biouh,
                          const float* __restrict__ Wfx,   const float* __restrict__ bfx,
                          const float* __restrict__ bfh,
                          const float* __restrict__ Wfh) {
  __shared__ float xs[4][DIM];
  const int v0 = blockIdx.x * 4, t = threadIdx.x;
  #pragma unroll
  for (int j = 0; j < 4; ++j) xs[j][t] = emb[(v0 + j) * DIM + t];
  __syncthreads();

  const float b0 = bioux[t]           + biouh[t];
  const float b1 = bioux[DIM + t]     + biouh[DIM + t];
  const float b2 = bioux[2*DIM + t]   + biouh[2*DIM + t];
  const float bf = bfx[t] + bfh[t];
  float a0[4], a1[4], a2[4], af[4];
  #pragma unroll
  for (int j = 0; j < 4; ++j) { a0[j] = b0; a1[j] = b1; a2[j] = b2; af[j] = bf; }

  #pragma unroll 4
  for (int k = 0; k < DIM; ++k) {
    const float w0 = Wioux[k*DIM3 + t];
    const float w1 = Wioux[k*DIM3 + DIM + t];
    const float w2 = Wioux[k*DIM3 + 2*DIM + t];
    const float wf = Wfx  [k*DIM + t];
    #pragma unroll
    for (int j = 0; j < 4; ++j) {
      const float xv = xs[j][k];
      a0[j] = fmaf(xv, w0, a0[j]);
      a1[j] = fmaf(xv, w1, a1[j]);
      a2[j] = fmaf(xv, w2, a2[j]);
      af[j] = fmaf(xv, wf, af[j]);
    }
  }

  float hj[4];
  #pragma unroll
  for (int j = 0; j < 4; ++j) {
    const int v = v0 + j;
    g_embp_iou[v*DIM3 + t]         = a0[j];
    g_embp_iou[v*DIM3 + DIM + t]   = a1[j];
    g_embp_iou[v*DIM3 + 2*DIM + t] = a2[j];
    g_embp_fx [v*DIM + t]          = af[j];
    const float c = sigm(a0[j]) * tanhf(a2[j]);   // leaf: h_sum=0, fc_sum=0
    const float h = sigm(a1[j]) * tanhf(c);
    g_leaf_c[v*DIM + t] = c;
    g_leaf_h[v*DIM + t] = h;
    hj[j] = h;
  }
  __syncthreads();
  #pragma unroll
  for (int j = 0; j < 4; ++j) xs[j][t] = hj[j];
  __syncthreads();

  float fp[4] = {0.f, 0.f, 0.f, 0.f};
  #pragma unroll 4
  for (int k = 0; k < DIM; ++k) {
    const float wf = Wfh[k*DIM + t];
    #pragma unroll
    for (int j = 0; j < 4; ++j) fp[j] = fmaf(xs[j][k], wf, fp[j]);
  }
  #pragma unroll
  for (int j = 0; j < 4; ++j) g_fpreL[(v0 + j)*DIM + t] = fp[j];
}

// ---------------- phase 1: depth + parent/token + child counts ----------------
__global__ void k_depth(const int* __restrict__ lpar, const int* __restrict__ rpar,
                        const int* __restrict__ ltok, const int* __restrict__ rtok) {
  const int g = blockIdx.x * blockDim.x + threadIdx.x;
  if (g >= 2 * NN) return;
  const int tree = g >> 16, node = g & (NN - 1);
  const int* par = tree ? rpar : lpar;
  const int* tok = tree ? rtok : ltok;
  int d = 0, i = node;
  while (i != 0) { i = par[i]; ++d; }
  if (d > MAXLV - 1) d = MAXLV - 1;
  g_depth[g] = d;
  g_par[g] = (tree << 16) | par[node];
  g_tok[g] = tok[node];
  if (node != 0) atomicAdd(&g_childcnt[(tree << 16) | par[node]], 1);
}

// ---------------- phase 1b: histogram of INTERNAL nodes only ----------------
__global__ void k_hist() {
  const int g = blockIdx.x * blockDim.x + threadIdx.x;
  if (g >= 2 * NN) return;
  if (g_childcnt[g] > 0)
    atomicAdd(&g_cnt[(g >> 16) * MAXLV + g_depth[g]], 1);
}

// ---------------- phase 2: level offsets (descending depth layout) ----------------
__global__ void k_scan() {
  if (threadIdx.x == 0 && blockIdx.x == 0) {
    int off = 0;
    for (int L = MAXLV - 1; L >= 0; --L) {
      g_lo[L] = off;
      g_start[0 * MAXLV + L] = off; off += g_cnt[0 * MAXLV + L];
      g_start[1 * MAXLV + L] = off; off += g_cnt[1 * MAXLV + L];
      g_hi[L] = off;
    }
  }
}

// ---------------- phase 3: bucket INTERNAL nodes by level ----------------
__global__ void k_scatter() {
  const int g = blockIdx.x * blockDim.x + threadIdx.x;
  if (g >= 2 * NN) return;
  if (g_childcnt[g] == 0) return;   // leaves handled by bulk pass
  const int tree = g >> 16;
  const int d = g_depth[g];
  const int pos = g_start[tree * MAXLV + d] + atomicAdd(&g_cur[tree * MAXLV + d], 1);
  g_sched[pos] = g;
}

// ---------------- phase 3b: bulk leaf pass (no matvecs!) ----------------
// Leaf h/c/fpre are pure token gathers; contribute to parent sums via atomics.
// Valid before the wavefront: every parent is processed at a strictly later wave.
__global__ void k_leaf() {
  const int node = blockIdx.x * 4 + (threadIdx.x >> 6);
  if (node >= 2 * NN) return;
  if (g_childcnt[node] != 0) return;         // internal (root is never a leaf)
  const int t4 = (threadIdx.x & 63) * 4;
  const int pg = g_par[node];
  const int v  = g_tok[node];
  const int pv = g_tok[pg];
  const float4 h4 = *(const float4*)&g_leaf_h [v  * DIM + t4];
  const float4 c4 = *(const float4*)&g_leaf_c [v  * DIM + t4];
  const float4 fp = *(const float4*)&g_fpreL  [v  * DIM + t4];
  const float4 fx = *(const float4*)&g_embp_fx[pv * DIM + t4];
  float* hs = &g_hsum [pg * DIM + t4];
  float* fc = &g_fcsum[pg * DIM + t4];
  atomicAdd(hs + 0, h4.x); atomicAdd(hs + 1, h4.y);
  atomicAdd(hs + 2, h4.z); atomicAdd(hs + 3, h4.w);
  atomicAdd(fc + 0, sigm(fp.x + fx.x) * c4.x);
  atomicAdd(fc + 1, sigm(fp.y + fx.y) * c4.y);
  atomicAdd(fc + 2, sigm(fp.z + fx.z) * c4.z);
  atomicAdd(fc + 3, sigm(fp.w + fx.w) * c4.w);
}

// ---------------- software grid barrier (grid sized to guaranteed residency) ----------------
__device__ __forceinline__ void gbar() {
  __threadfence();
  __syncthreads();
  if (threadIdx.x == 0) {
    volatile unsigned* vg = &g_bargen;
    const unsigned my = *vg;
    const unsigned tkt = atomicAdd(&g_barcnt, 1u);
    if (tkt == gridDim.x - 1) {
      g_barcnt = 0;
      __threadfence();
      atomicAdd(&g_bargen, 1u);
    } else {
      while (*vg == my) { __nanosleep(64); }
    }
    __threadfence();
  }
  __syncthreads();
}

// ---------------- phase 4: persistent wavefront (internal nodes, f32x2) ----------------
__global__ void __launch_bounds__(256, 2) k_levels(const float* __restrict__ Wiouh,
                                                   const float* __restrict__ Wfh) {
  __shared__ __align__(16) float hT[DIM][PAD];   // transposed h staging (row stride 80B, 16B-mult)
  __shared__ int snode[TB], spar[TB], stok[TB], sptok[TB];
  const int t = threadIdx.x;

  for (int L = MAXLV - 1; L >= 0; --L) {
    const int lo = g_lo[L], hi = g_hi[L];
    if (hi == lo) continue;                  // identical on all blocks
    const int nch = (hi - lo + TB - 1) / TB;

    for (int ch = blockIdx.x; ch < nch; ch += gridDim.x) {
      const int base = lo + ch * TB;
      __syncthreads();                       // previous chunk done with shared

      if (t < TB) {
        const int gg = (base + t < hi) ? g_sched[base + t] : -1;
        snode[t] = gg;
        if (gg >= 0) {
          const int pg = g_par[gg];
          spar[t] = pg; stok[t] = g_tok[gg]; sptok[t] = g_tok[pg];
        }
      }
      __syncthreads();

      // load child-sum h, transposed (cross-SM atomics -> L2-coherent loads)
      #pragma unroll
      for (int b = 0; b < TB; ++b) {
        const int gg = snode[b];
        hT[t][b] = (gg >= 0) ? __ldcg(&g_hsum[gg * DIM + t]) : 0.0f;
      }

      // init iou accumulators from embedding projection (biases folded), packed by node pair
      unsigned long long A0[8], A1[8], A2[8];
      #pragma unroll
      for (int p = 0; p < 8; ++p) {
        float e00 = 0.f, e01 = 0.f, e10 = 0.f, e11 = 0.f, e20 = 0.f, e21 = 0.f;
        if (snode[2*p] >= 0) {
          const int tv = stok[2*p] * DIM3;
          e00 = g_embp_iou[tv + t]; e10 = g_embp_iou[tv + DIM + t]; e20 = g_embp_iou[tv + 2*DIM + t];
        }
        if (snode[2*p+1] >= 0) {
          const int tv = stok[2*p+1] * DIM3;
          e01 = g_embp_iou[tv + t]; e11 = g_embp_iou[tv + DIM + t]; e21 = g_embp_iou[tv + 2*DIM + t];
        }
        A0[p] = pack2(e00, e01); A1[p] = pack2(e10, e11); A2[p] = pack2(e20, e21);
      }
      __syncthreads();

      // matvec 1: iou += h_sum @ Wiouh  (thread t owns cols t, 256+t, 512+t; FFMA2 over node pairs)
      #pragma unroll 2
      for (int k = 0; k < DIM; ++k) {
        const float* wr = Wiouh + k * DIM3 + t;
        const float w0 = __ldg(wr), w1 = __ldg(wr + DIM), w2 = __ldg(wr + 2*DIM);
        const unsigned long long W0 = pack2(w0, w0), W1 = pack2(w1, w1), W2 = pack2(w2, w2);
        const ulonglong2* hr = reinterpret_cast<const ulonglong2*>(&hT[k][0]);
        const ulonglong2 hA = hr[0], hB = hr[1], hC = hr[2], hD = hr[3];
        FMA2(A0[0], hA.x, W0); FMA2(A1[0], hA.x, W1); FMA2(A2[0], hA.x, W2);
        FMA2(A0[1], hA.y, W0); FMA2(A1[1], hA.y, W1); FMA2(A2[1], hA.y, W2);
        FMA2(A0[2], hB.x, W0); FMA2(A1[2], hB.x, W1); FMA2(A2[2], hB.x, W2);
        FMA2(A0[3], hB.y, W0); FMA2(A1[3], hB.y, W1); FMA2(A2[3], hB.y, W2);
        FMA2(A0[4], hC.x, W0); FMA2(A1[4], hC.x, W1); FMA2(A2[4], hC.x, W2);
        FMA2(A0[5], hC.y, W0); FMA2(A1[5], hC.y, W1); FMA2(A2[5], hC.y, W2);
        FMA2(A0[6], hD.x, W0); FMA2(A1[6], hD.x, W1); FMA2(A2[6], hD.x, W2);
        FMA2(A0[7], hD.y, W0); FMA2(A1[7], hD.y, W1); FMA2(A2[7], hD.y, W2);
      }

      // gates
      float cc[TB], hh[TB];
      #pragma unroll
      for (int p = 0; p < 8; ++p) {
        float a0l, a0h, a1l, a1h, a2l, a2h;
        unpack2(A0[p], a0l, a0h);
        unpack2(A1[p], a1l, a1h);
        unpack2(A2[p], a2l, a2h);
        {
          const int b = 2*p; const int gg = snode[b];
          const float fcs = (gg >= 0) ? __ldcg(&g_fcsum[gg * DIM + t]) : 0.f;
          const float c = sigm(a0l) * tanhf(a2l) + fcs;
          const float h = sigm(a1l) * tanhf(c);
          cc[b] = c; hh[b] = h;
        }
        {
          const int b = 2*p + 1; const int gg = snode[b];
          const float fcs = (gg >= 0) ? __ldcg(&g_fcsum[gg * DIM + t]) : 0.f;
          const float c = sigm(a0h) * tanhf(a2h) + fcs;
          const float h = sigm(a1h) * tanhf(c);
          cc[b] = c; hh[b] = h;
        }
      }
      __syncthreads();                       // all threads finished reading old hT
      #pragma unroll
      for (int b = 0; b < TB; ++b) hT[t][b] = hh[b];
      __syncthreads();

      // matvec 2: fpre = h @ Wfh + folded(embp_fx[parent_tok])
      unsigned long long F[8];
      #pragma unroll
      for (int p = 0; p < 8; ++p) {
        const float f0 = (snode[2*p]   >= 0) ? g_embp_fx[sptok[2*p]   * DIM + t] : 0.f;
        const float f1 = (snode[2*p+1] >= 0) ? g_embp_fx[sptok[2*p+1] * DIM + t] : 0.f;
        F[p] = pack2(f0, f1);
      }
      #pragma unroll 2
      for (int k = 0; k < DIM; ++k) {
        const float wf = __ldg(Wfh + k * DIM + t);
        const unsigned long long Wf = pack2(wf, wf);
        const ulonglong2* hr = reinterpret_cast<const ulonglong2*>(&hT[k][0]);
        const ulonglong2 hA = hr[0], hB = hr[1], hC = hr[2], hD = hr[3];
        FMA2(F[0], hA.x, Wf); FMA2(F[1], hA.y, Wf);
        FMA2(F[2], hB.x, Wf); FMA2(F[3], hB.y, Wf);
        FMA2(F[4], hC.x, Wf); FMA2(F[5], hC.y, Wf);
        FMA2(F[6], hD.x, Wf); FMA2(F[7], hD.y, Wf);
      }

      // accumulate into parents (siblings at same level may collide -> atomics)
      #pragma unroll
      for (int p = 0; p < 8; ++p) {
        float fl, fh2;
        unpack2(F[p], fl, fh2);
        #pragma unroll
        for (int q = 0; q < 2; ++q) {
          const int b = 2*p + q;
          const int gg = snode[b];
          if (gg < 0) continue;
          const float fv = q ? fh2 : fl;
          if ((gg & (NN - 1)) == 0) {
            g_croot[(gg >> 16) * DIM + t] = cc[b];     // tree root: record c
          } else {
            atomicAdd(&g_hsum [spar[b] * DIM + t], hh[b]);
            atomicAdd(&g_fcsum[spar[b] * DIM + t], sigm(fv) * cc[b]);
          }
        }
      }
    }
    gbar();   // level complete on the whole grid
  }
}

// ---------------- phase 5: similarity head ----------------
__global__ void k_head(const float* __restrict__ Wh, const float* __restrict__ bh,
                       const float* __restrict__ Wp, const float* __restrict__ bp,
                       float* __restrict__ out) {
  __shared__ float vec[2 * DIM];
  __shared__ float s0[DIM], s1[DIM];
  const int t = threadIdx.x;
  const float cl = g_croot[t], cr = g_croot[DIM + t];
  vec[t] = cl * cr;
  vec[DIM + t] = fabsf(cl - cr);
  __syncthreads();
  float acc = bh[t];
  #pragma unroll 4
  for (int k = 0; k < 2 * DIM; ++k) acc = fmaf(vec[k], Wh[k * DIM + t], acc);
  const float hid = sigm(acc);
  s0[t] = hid * Wp[t * 2 + 0];
  s1[t] = hid * Wp[t * 2 + 1];
  __syncthreads();
  for (int s = DIM / 2; s > 0; s >>= 1) {
    if (t < s) { s0[t] += s0[t + s]; s1[t] += s1[t + s]; }
    __syncthreads();
  }
  if (t == 0) {
    const float l0 = s0[0] + bp[0], l1 = s1[0] + bp[1];
    const float m = fmaxf(l0, l1);
    const float e0 = expf(l0 - m), e1 = expf(l1 - m);
    const float inv = 1.0f / (e0 + e1);
    out[0] = e0 * inv;
    out[1] = e1 * inv;
  }
}

// ---------------- launcher (graph-capturable: launches + async memsets only) ----------------
extern "C" void kernel_launch(void* const* d_in, const int* in_sizes, int n_in,
                              void* d_out, int out_size) {
  (void)in_sizes; (void)n_in;
  const int*   l_tok = (const int*)  d_in[0];
  const int*   l_par = (const int*)  d_in[1];
  const int*   r_tok = (const int*)  d_in[2];
  const int*   r_par = (const int*)  d_in[3];
  const float* emb   = (const float*)d_in[4];
  const float* Wioux = (const float*)d_in[5];
  const float* bioux = (const float*)d_in[6];
  const float* Wiouh = (const float*)d_in[7];
  const float* biouh = (const float*)d_in[8];
  const float* Wfx   = (const float*)d_in[9];
  const float* bfx   = (const float*)d_in[10];
  const float* Wfh   = (const float*)d_in[11];
  const float* bfh   = (const float*)d_in[12];
  const float* Wh    = (const float*)d_in[13];
  const float* bh    = (const float*)d_in[14];
  const float* Wp    = (const float*)d_in[15];
  const float* bp    = (const float*)d_in[16];
  float* out = (float*)d_out;
  (void)out_size;

  void *p_hs, *p_fc, *p_cnt, *p_cur, *p_cc;
  cudaGetSymbolAddress(&p_hs,  g_hsum);
  cudaGetSymbolAddress(&p_fc,  g_fcsum);
  cudaGetSymbolAddress(&p_cnt, g_cnt);
  cudaGetSymbolAddress(&p_cur, g_cur);
  cudaGetSymbolAddress(&p_cc,  g_childcnt);
  cudaMemsetAsync(p_hs,  0, sizeof(float) * 2ull * NN * DIM);
  cudaMemsetAsync(p_fc,  0, sizeof(float) * 2ull * NN * DIM);
  cudaMemsetAsync(p_cnt, 0, sizeof(int) * 2 * MAXLV);
  cudaMemsetAsync(p_cur, 0, sizeof(int) * 2 * MAXLV);
  cudaMemsetAsync(p_cc,  0, sizeof(int) * 2 * NN);

  k_embproj<<<VOCAB / 4, DIM>>>(emb, Wioux, bioux, biouh, Wfx, bfx, bfh, Wfh);
  k_depth<<<(2 * NN + 255) / 256, 256>>>(l_par, r_par, l_tok, r_tok);
  k_hist<<<(2 * NN + 255) / 256, 256>>>();
  k_scan<<<1, 32>>>();
  k_scatter<<<(2 * NN + 255) / 256, 256>>>();
  k_leaf<<<(2 * NN + 3) / 4, 256>>>();

  int dev = 0;
  cudaGetDevice(&dev);
  int sms = 148;
  cudaDeviceGetAttribute(&sms, cudaDevAttrMultiProcessorCount, dev);
  int maxb = 1;
  cudaOccupancyMaxActiveBlocksPerMultiprocessor(&maxb, k_levels, 256, 0);
  if (maxb > 2) maxb = 2;
  if (maxb < 1) maxb = 1;
  k_levels<<<sms * maxb, 256>>>(Wiouh, Wfh);   // grid == guaranteed-resident blocks (gbar-safe)

  k_head<<<1, DIM>>>(Wh, bh, Wp, bp, out);
}

// round 7
// speedup vs baseline: 1.4676x; 1.3151x over previous
#include <cuda_runtime.h>

#define NN     65536
#define VOCAB  1000
#define DIM    256
#define DIM3   768
#define MAXLV  192
#define TB     16
#define PAD    20
#define EMBB   (VOCAB / 4)        // 250 embproj blocks
#define DEPB   (2 * NN / 256)     // 512 depth blocks

// ---------------- scratch (static device allocations only) ----------------
static __device__ float g_hsum [2 * NN * DIM];    // child h sums   (134 MB)
static __device__ float g_fcsum[2 * NN * DIM];    // child f*c sums (134 MB)
static __device__ float g_embp_iou[VOCAB * DIM3]; // emb@Wioux + bioux + biouh
static __device__ float g_embp_fx [VOCAB * DIM];  // emb@Wfx   + bfx   + bfh
static __device__ float g_leaf_c  [VOCAB * DIM];  // leaf cell state per token
static __device__ float g_leaf_h  [VOCAB * DIM];  // leaf hidden per token
static __device__ float g_fpreL   [VOCAB * DIM];  // leaf_h @ Wfh per token
static __device__ int   g_sched[2 * NN];
static __device__ int   g_par  [2 * NN];
static __device__ int   g_tok  [2 * NN];
static __device__ int   g_depth[2 * NN];
static __device__ int   g_mark [2 * NN];          // 1 = internal node
static __device__ int   g_cnt  [2 * MAXLV];
static __device__ int   g_cur  [2 * MAXLV];
static __device__ int   g_start[2 * MAXLV];
static __device__ int   g_lo[MAXLV];
static __device__ int   g_hi[MAXLV];
static __device__ float g_croot[2 * DIM];
static __device__ unsigned g_barcnt;   // zero-init, self-resetting
static __device__ unsigned g_bargen;   // monotone generation counter

__device__ __forceinline__ float sigm(float x) { return 1.0f / (1.0f + expf(-x)); }

// ---- f32x2 helpers (sm_100+; ptxas never auto-fuses FFMA2 from C++) ----
__device__ __forceinline__ unsigned long long pack2(float lo, float hi) {
  unsigned long long r;
  asm("mov.b64 %0, {%1, %2};" : "=l"(r) : "f"(lo), "f"(hi));
  return r;
}
__device__ __forceinline__ void unpack2(unsigned long long v, float& lo, float& hi) {
  asm("mov.b64 {%0, %1}, %2;" : "=f"(lo), "=f"(hi) : "l"(v));
}
#define FMA2(d, h, w) asm("fma.rn.f32x2 %0, %1, %2, %0;" : "+l"(d) : "l"(h), "l"(w))

// ---------------- phase 1 (FUSED): embedding projections  ∥  depth+hist ----------------
// blocks [0, EMBB): per-vocab projections + leaf tables (4 tokens/block)
// blocks [EMBB, EMBB+DEPB): node depth, parent/token staging, internal-node
//   marking via first-touch atomicExch + per-(tree,level) internal histogram.
__global__ void k_prep(const float* __restrict__ emb,
                       const float* __restrict__ Wioux, const float* __restrict__ bioux,
                       const float* __restrict__ biouh,
                       const float* __restrict__ Wfx,   const float* __restrict__ bfx,
                       const float* __restrict__ bfh,
                       const float* __restrict__ Wfh,
                       const int* __restrict__ lpar, const int* __restrict__ rpar,
                       const int* __restrict__ ltok, const int* __restrict__ rtok) {
  const int t = threadIdx.x;
  if (blockIdx.x < EMBB) {
    // ---- embproj part ----
    __shared__ float xs[4][DIM];
    const int v0 = blockIdx.x * 4;
    #pragma unroll
    for (int j = 0; j < 4; ++j) xs[j][t] = emb[(v0 + j) * DIM + t];
    __syncthreads();

    const float b0 = bioux[t]           + biouh[t];
    const float b1 = bioux[DIM + t]     + biouh[DIM + t];
    const float b2 = bioux[2*DIM + t]   + biouh[2*DIM + t];
    const float bf = bfx[t] + bfh[t];
    float a0[4], a1[4], a2[4], af[4];
    #pragma unroll
    for (int j = 0; j < 4; ++j) { a0[j] = b0; a1[j] = b1; a2[j] = b2; af[j] = bf; }

    #pragma unroll 4
    for (int k = 0; k < DIM; ++k) {
      const float w0 = Wioux[k*DIM3 + t];
      const float w1 = Wioux[k*DIM3 + DIM + t];
      const float w2 = Wioux[k*DIM3 + 2*DIM + t];
      const float wf = Wfx  [k*DIM + t];
      #pragma unroll
      for (int j = 0; j < 4; ++j) {
        const float xv = xs[j][k];
        a0[j] = fmaf(xv, w0, a0[j]);
        a1[j] = fmaf(xv, w1, a1[j]);
        a2[j] = fmaf(xv, w2, a2[j]);
        af[j] = fmaf(xv, wf, af[j]);
      }
    }

    float hj[4];
    #pragma unroll
    for (int j = 0; j < 4; ++j) {
      const int v = v0 + j;
      g_embp_iou[v*DIM3 + t]         = a0[j];
      g_embp_iou[v*DIM3 + DIM + t]   = a1[j];
      g_embp_iou[v*DIM3 + 2*DIM + t] = a2[j];
      g_embp_fx [v*DIM + t]          = af[j];
      const float c = sigm(a0[j]) * tanhf(a2[j]);   // leaf: h_sum=0, fc_sum=0
      const float h = sigm(a1[j]) * tanhf(c);
      g_leaf_c[v*DIM + t] = c;
      g_leaf_h[v*DIM + t] = h;
      hj[j] = h;
    }
    __syncthreads();
    #pragma unroll
    for (int j = 0; j < 4; ++j) xs[j][t] = hj[j];
    __syncthreads();

    float fp[4] = {0.f, 0.f, 0.f, 0.f};
    #pragma unroll 4
    for (int k = 0; k < DIM; ++k) {
      const float wf = Wfh[k*DIM + t];
      #pragma unroll
      for (int j = 0; j < 4; ++j) fp[j] = fmaf(xs[j][k], wf, fp[j]);
    }
    #pragma unroll
    for (int j = 0; j < 4; ++j) g_fpreL[(v0 + j)*DIM + t] = fp[j];
  } else {
    // ---- depth + hist part ----
    const int g = (blockIdx.x - EMBB) * 256 + t;
    const int tree = g >> 16, node = g & (NN - 1);
    const int* par = tree ? rpar : lpar;
    const int* tok = tree ? rtok : ltok;
    int d = 0, i = node;
    while (i != 0) { i = par[i]; ++d; }   // parent[i] < i guarantees termination
    if (d > MAXLV - 1) d = MAXLV - 1;
    g_depth[g] = d;
    g_par[g] = (tree << 16) | par[node];
    g_tok[g] = tok[node];
    if (node != 0) {
      // first-touch: exactly one child counts its parent (depth d-1) as internal
      const int pg = (tree << 16) | par[node];
      if (atomicExch(&g_mark[pg], 1) == 0)
        atomicAdd(&g_cnt[tree * MAXLV + (d - 1)], 1);
    }
  }
}

// ---------------- phase 2: level offsets (descending depth layout) ----------------
__global__ void k_scan() {
  if (threadIdx.x == 0 && blockIdx.x == 0) {
    int off = 0;
    for (int L = MAXLV - 1; L >= 0; --L) {
      g_lo[L] = off;
      g_start[0 * MAXLV + L] = off; off += g_cnt[0 * MAXLV + L];
      g_start[1 * MAXLV + L] = off; off += g_cnt[1 * MAXLV + L];
      g_hi[L] = off;
    }
  }
}

// ---------------- phase 3 (FUSED): bucket internal nodes  ∥  bulk leaf pass ----------------
// blocks [0, DEPB): scatter internal nodes by level.
// blocks [DEPB, ...): leaves contribute h / f*c to parents via atomics
//   (valid before the wavefront: every parent runs at a strictly later wave).
__global__ void k_scatlf() {
  const int t = threadIdx.x;
  if (blockIdx.x < DEPB) {
    const int g = blockIdx.x * 256 + t;
    if (g_mark[g] == 0) return;       // leaves handled below
    const int tree = g >> 16;
    const int d = g_depth[g];
    const int pos = g_start[tree * MAXLV + d] + atomicAdd(&g_cur[tree * MAXLV + d], 1);
    g_sched[pos] = g;
  } else {
    const int node = (blockIdx.x - DEPB) * 4 + (t >> 6);
    if (node >= 2 * NN) return;
    if (g_mark[node] != 0) return;    // internal (roots are internal)
    const int t4 = (t & 63) * 4;
    const int pg = g_par[node];
    const int v  = g_tok[node];
    const int pv = g_tok[pg];
    const float4 h4 = *(const float4*)&g_leaf_h [v  * DIM + t4];
    const float4 c4 = *(const float4*)&g_leaf_c [v  * DIM + t4];
    const float4 fp = *(const float4*)&g_fpreL  [v  * DIM + t4];
    const float4 fx = *(const float4*)&g_embp_fx[pv * DIM + t4];
    float* hs = &g_hsum [pg * DIM + t4];
    float* fc = &g_fcsum[pg * DIM + t4];
    atomicAdd(hs + 0, h4.x); atomicAdd(hs + 1, h4.y);
    atomicAdd(hs + 2, h4.z); atomicAdd(hs + 3, h4.w);
    atomicAdd(fc + 0, sigm(fp.x + fx.x) * c4.x);
    atomicAdd(fc + 1, sigm(fp.y + fx.y) * c4.y);
    atomicAdd(fc + 2, sigm(fp.z + fx.z) * c4.z);
    atomicAdd(fc + 3, sigm(fp.w + fx.w) * c4.w);
  }
}

// ---------------- software grid barrier (grid sized to guaranteed residency) ----------------
__device__ __forceinline__ void gbar() {
  __threadfence();
  __syncthreads();
  if (threadIdx.x == 0) {
    volatile unsigned* vg = &g_bargen;
    const unsigned my = *vg;
    const unsigned tkt = atomicAdd(&g_barcnt, 1u);
    if (tkt == gridDim.x - 1) {
      g_barcnt = 0;
      __threadfence();
      atomicAdd(&g_bargen, 1u);
    } else {
      while (*vg == my) { __nanosleep(64); }
    }
    __threadfence();
  }
  __syncthreads();
}

// ---------------- phase 4: persistent wavefront (internal nodes, f32x2) ----------------
__global__ void __launch_bounds__(256, 2) k_levels(const float* __restrict__ Wiouh,
                                                   const float* __restrict__ Wfh) {
  __shared__ __align__(16) float hT[DIM][PAD];   // transposed h staging (row stride 80B)
  __shared__ float fcsh[TB][DIM];                // fcsum prefetch (16 KB)
  __shared__ int snode[TB], spar[TB], stok[TB], sptok[TB];
  const int t = threadIdx.x;

  for (int L = MAXLV - 1; L >= 0; --L) {
    const int lo = g_lo[L], hi = g_hi[L];
    if (hi == lo) continue;                  // identical on all blocks
    const int nch = (hi - lo + TB - 1) / TB;

    for (int ch = blockIdx.x; ch < nch; ch += gridDim.x) {
      const int base = lo + ch * TB;
      __syncthreads();                       // previous chunk done with shared

      if (t < TB) {
        const int gg = (base + t < hi) ? g_sched[base + t] : -1;
        snode[t] = gg;
        if (gg >= 0) {
          const int pg = g_par[gg];
          spar[t] = pg; stok[t] = g_tok[gg]; sptok[t] = g_tok[pg];
        }
      }
      __syncthreads();

      // load child-sum h (transposed) + fcsum (cross-SM atomics -> L2-coherent loads)
      #pragma unroll
      for (int b = 0; b < TB; ++b) {
        const int gg = snode[b];
        hT[t][b]   = (gg >= 0) ? __ldcg(&g_hsum [gg * DIM + t]) : 0.0f;
        fcsh[b][t] = (gg >= 0) ? __ldcg(&g_fcsum[gg * DIM + t]) : 0.0f;
      }

      // init iou accumulators from embedding projection (biases folded), packed by node pair
      unsigned long long A0[8], A1[8], A2[8];
      #pragma unroll
      for (int p = 0; p < 8; ++p) {
        float e00 = 0.f, e01 = 0.f, e10 = 0.f, e11 = 0.f, e20 = 0.f, e21 = 0.f;
        if (snode[2*p] >= 0) {
          const int tv = stok[2*p] * DIM3;
          e00 = g_embp_iou[tv + t]; e10 = g_embp_iou[tv + DIM + t]; e20 = g_embp_iou[tv + 2*DIM + t];
        }
        if (snode[2*p+1] >= 0) {
          const int tv = stok[2*p+1] * DIM3;
          e01 = g_embp_iou[tv + t]; e11 = g_embp_iou[tv + DIM + t]; e21 = g_embp_iou[tv + 2*DIM + t];
        }
        A0[p] = pack2(e00, e01); A1[p] = pack2(e10, e11); A2[p] = pack2(e20, e21);
      }
      __syncthreads();

      // matvec 1: iou += h_sum @ Wiouh  (thread t owns cols t, 256+t, 512+t; FFMA2 over node pairs)
      #pragma unroll 4
      for (int k = 0; k < DIM; ++k) {
        const float* wr = Wiouh + k * DIM3 + t;
        const float w0 = __ldg(wr), w1 = __ldg(wr + DIM), w2 = __ldg(wr + 2*DIM);
        const unsigned long long W0 = pack2(w0, w0), W1 = pack2(w1, w1), W2 = pack2(w2, w2);
        const ulonglong2* hr = reinterpret_cast<const ulonglong2*>(&hT[k][0]);
        const ulonglong2 hA = hr[0], hB = hr[1], hC = hr[2], hD = hr[3];
        FMA2(A0[0], hA.x, W0); FMA2(A1[0], hA.x, W1); FMA2(A2[0], hA.x, W2);
        FMA2(A0[1], hA.y, W0); FMA2(A1[1], hA.y, W1); FMA2(A2[1], hA.y, W2);
        FMA2(A0[2], hB.x, W0); FMA2(A1[2], hB.x, W1); FMA2(A2[2], hB.x, W2);
        FMA2(A0[3], hB.y, W0); FMA2(A1[3], hB.y, W1); FMA2(A2[3], hB.y, W2);
        FMA2(A0[4], hC.x, W0); FMA2(A1[4], hC.x, W1); FMA2(A2[4], hC.x, W2);
        FMA2(A0[5], hC.y, W0); FMA2(A1[5], hC.y, W1); FMA2(A2[5], hC.y, W2);
        FMA2(A0[6], hD.x, W0); FMA2(A1[6], hD.x, W1); FMA2(A2[6], hD.x, W2);
        FMA2(A0[7], hD.y, W0); FMA2(A1[7], hD.y, W1); FMA2(A2[7], hD.y, W2);
      }

      // gates
      float cc[TB], hh[TB];
      #pragma unroll
      for (int p = 0; p < 8; ++p) {
        float a0l, a0h, a1l, a1h, a2l, a2h;
        unpack2(A0[p], a0l, a0h);
        unpack2(A1[p], a1l, a1h);
        unpack2(A2[p], a2l, a2h);
        {
          const int b = 2*p;
          const float c = sigm(a0l) * tanhf(a2l) + fcsh[b][t];
          const float h = sigm(a1l) * tanhf(c);
          cc[b] = c; hh[b] = h;
        }
        {
          const int b = 2*p + 1;
          const float c = sigm(a0h) * tanhf(a2h) + fcsh[b][t];
          const float h = sigm(a1h) * tanhf(c);
          cc[b] = c; hh[b] = h;
        }
      }
      __syncthreads();                       // all threads finished reading old hT
      #pragma unroll
      for (int b = 0; b < TB; ++b) hT[t][b] = hh[b];
      __syncthreads();

      // matvec 2: fpre = h @ Wfh + folded(embp_fx[parent_tok])
      unsigned long long F[8];
      #pragma unroll
      for (int p = 0; p < 8; ++p) {
        const float f0 = (snode[2*p]   >= 0) ? g_embp_fx[sptok[2*p]   * DIM + t] : 0.f;
        const float f1 = (snode[2*p+1] >= 0) ? g_embp_fx[sptok[2*p+1] * DIM + t] : 0.f;
        F[p] = pack2(f0, f1);
      }
      #pragma unroll 4
      for (int k = 0; k < DIM; ++k) {
        const float wf = __ldg(Wfh + k * DIM + t);
        const unsigned long long Wf = pack2(wf, wf);
        const ulonglong2* hr = reinterpret_cast<const ulonglong2*>(&hT[k][0]);
        const ulonglong2 hA = hr[0], hB = hr[1], hC = hr[2], hD = hr[3];
        FMA2(F[0], hA.x, Wf); FMA2(F[1], hA.y, Wf);
        FMA2(F[2], hB.x, Wf); FMA2(F[3], hB.y, Wf);
        FMA2(F[4], hC.x, Wf); FMA2(F[5], hC.y, Wf);
        FMA2(F[6], hD.x, Wf); FMA2(F[7], hD.y, Wf);
      }

      // accumulate into parents (siblings at same level may collide -> atomics)
      #pragma unroll
      for (int p = 0; p < 8; ++p) {
        float fl, fh2;
        unpack2(F[p], fl, fh2);
        #pragma unroll
        for (int q = 0; q < 2; ++q) {
          const int b = 2*p + q;
          const int gg = snode[b];
          if (gg < 0) continue;
          const float fv = q ? fh2 : fl;
          if ((gg & (NN - 1)) == 0) {
            g_croot[(gg >> 16) * DIM + t] = cc[b];     // tree root: record c
          } else {
            atomicAdd(&g_hsum [spar[b] * DIM + t], hh[b]);
            atomicAdd(&g_fcsum[spar[b] * DIM + t], sigm(fv) * cc[b]);
          }
        }
      }
    }
    gbar();   // level complete on the whole grid
  }
}

// ---------------- phase 5: similarity head ----------------
__global__ void k_head(const float* __restrict__ Wh, const float* __restrict__ bh,
                       const float* __restrict__ Wp, const float* __restrict__ bp,
                       float* __restrict__ out) {
  __shared__ float vec[2 * DIM];
  __shared__ float s0[DIM], s1[DIM];
  const int t = threadIdx.x;
  const float cl = g_croot[t], cr = g_croot[DIM + t];
  vec[t] = cl * cr;
  vec[DIM + t] = fabsf(cl - cr);
  __syncthreads();
  float acc = bh[t];
  #pragma unroll 4
  for (int k = 0; k < 2 * DIM; ++k) acc = fmaf(vec[k], Wh[k * DIM + t], acc);
  const float hid = sigm(acc);
  s0[t] = hid * Wp[t * 2 + 0];
  s1[t] = hid * Wp[t * 2 + 1];
  __syncthreads();
  for (int s = DIM / 2; s > 0; s >>= 1) {
    if (t < s) { s0[t] += s0[t + s]; s1[t] += s1[t + s]; }
    __syncthreads();
  }
  if (t == 0) {
    const float l0 = s0[0] + bp[0], l1 = s1[0] + bp[1];
    const float m = fmaxf(l0, l1);
    const float e0 = expf(l0 - m), e1 = expf(l1 - m);
    const float inv = 1.0f / (e0 + e1);
    out[0] = e0 * inv;
    out[1] = e1 * inv;
  }
}

// ---------------- launcher (graph-capturable: launches + async memsets only) ----------------
extern "C" void kernel_launch(void* const* d_in, const int* in_sizes, int n_in,
                              void* d_out, int out_size) {
  (void)in_sizes; (void)n_in;
  const int*   l_tok = (const int*)  d_in[0];
  const int*   l_par = (const int*)  d_in[1];
  const int*   r_tok = (const int*)  d_in[2];
  const int*   r_par = (const int*)  d_in[3];
  const float* emb   = (const float*)d_in[4];
  const float* Wioux = (const float*)d_in[5];
  const float* bioux = (const float*)d_in[6];
  const float* Wiouh = (const float*)d_in[7];
  const float* biouh = (const float*)d_in[8];
  const float* Wfx   = (const float*)d_in[9];
  const float* bfx   = (const float*)d_in[10];
  const float* Wfh   = (const float*)d_in[11];
  const float* bfh   = (const float*)d_in[12];
  const float* Wh    = (const float*)d_in[13];
  const float* bh    = (const float*)d_in[14];
  const float* Wp    = (const float*)d_in[15];
  const float* bp    = (const float*)d_in[16];
  float* out = (float*)d_out;
  (void)out_size;

  void *p_hs, *p_fc, *p_cnt, *p_cur, *p_mk;
  cudaGetSymbolAddress(&p_hs,  g_hsum);
  cudaGetSymbolAddress(&p_fc,  g_fcsum);
  cudaGetSymbolAddress(&p_cnt, g_cnt);
  cudaGetSymbolAddress(&p_cur, g_cur);
  cudaGetSymbolAddress(&p_mk,  g_mark);
  cudaMemsetAsync(p_hs,  0, sizeof(float) * 2ull * NN * DIM);
  cudaMemsetAsync(p_fc,  0, sizeof(float) * 2ull * NN * DIM);
  cudaMemsetAsync(p_cnt, 0, sizeof(int) * 2 * MAXLV);
  cudaMemsetAsync(p_cur, 0, sizeof(int) * 2 * MAXLV);
  cudaMemsetAsync(p_mk,  0, sizeof(int) * 2 * NN);

  k_prep<<<EMBB + DEPB, 256>>>(emb, Wioux, bioux, biouh, Wfx, bfx, bfh, Wfh,
                               l_par, r_par, l_tok, r_tok);
  k_scan<<<1, 32>>>();
  k_scatlf<<<DEPB + (2 * NN + 3) / 4, 256>>>();

  int dev = 0;
  cudaGetDevice(&dev);
  int sms = 148;
  cudaDeviceGetAttribute(&sms, cudaDevAttrMultiProcessorCount, dev);
  int maxb = 1;
  cudaOccupancyMaxActiveBlocksPerMultiprocessor(&maxb, k_levels, 256, 0);
  if (maxb > 2) maxb = 2;
  if (maxb < 1) maxb = 1;
  k_levels<<<sms * maxb, 256>>>(Wiouh, Wfh);   // grid == guaranteed-resident blocks (gbar-safe)

  k_head<<<1, DIM>>>(Wh, bh, Wp, bp, out);
}